// round 5
// baseline (speedup 1.0000x reference)
#include <cuda_runtime.h>
#include <cstdint>

#define H 4096
#define NUM_LAYERS 8
#define ROWS 8                    // rows per block == warps per block
#define THREADS (ROWS * 32)       // 256
#define C 512                     // columns per K-tile
#define ROW_TILE_BYTES (C * 4)    // 2048 B per row per tile
#define TILE_BYTES (ROWS * ROW_TILE_BYTES)  // 16 KB
#define T_TILES (H / C)           // 8
#define STAGES 4

// Dynamic smem layout (byte offsets)
#define SMEM_X 0                                   // x vector: 16 KB
#define SMEM_STAGE(s) (16384 + (s) * TILE_BYTES)   // 4 x 16 KB weight stages
#define SMEM_MBAR (16384 + STAGES * TILE_BYTES)    // 4 mbarriers
#define SMEM_TOTAL (SMEM_MBAR + STAGES * 8 + 128)

// Ping-pong hidden-state buffers (allocation-free scratch).
__device__ float g_h[2][H];

__device__ __forceinline__ uint32_t smem_u32(const void* p) {
    uint32_t a;
    asm("{ .reg .u64 t; cvta.to.shared.u64 t, %1; cvt.u32.u64 %0, t; }"
        : "=r"(a) : "l"(p));
    return a;
}

__device__ __forceinline__ void mbar_init(uint32_t mbar, uint32_t count) {
    asm volatile("mbarrier.init.shared.b64 [%0], %1;" :: "r"(mbar), "r"(count) : "memory");
}

__device__ __forceinline__ void mbar_expect_tx(uint32_t mbar, uint32_t bytes) {
    asm volatile("mbarrier.arrive.expect_tx.shared.b64 _, [%0], %1;"
                 :: "r"(mbar), "r"(bytes) : "memory");
}

__device__ __forceinline__ void mbar_wait(uint32_t mbar, uint32_t parity) {
    asm volatile(
        "{\n\t.reg .pred P;\n\t"
        "W_%=:\n\t"
        "mbarrier.try_wait.parity.acquire.cta.shared::cta.b64 P, [%0], %1, 0x989680;\n\t"
        "@P bra D_%=;\n\t"
        "bra W_%=;\n\t"
        "D_%=:\n\t}"
        :: "r"(mbar), "r"(parity) : "memory");
}

// 1D bulk async copy global -> shared, completion via mbarrier tx-bytes.
__device__ __forceinline__ void bulk_cp(uint32_t dst_smem, const void* src_gmem,
                                        uint32_t bytes, uint32_t mbar) {
    asm volatile(
        "cp.async.bulk.shared::cluster.global.mbarrier::complete_tx::bytes "
        "[%0], [%1], %2, [%3];"
        :: "r"(dst_smem), "l"(src_gmem), "r"(bytes), "r"(mbar) : "memory");
}

// GEMV via TMA bulk-copy pipeline: weights stream gmem->smem with
// cp.async.bulk (bypasses the per-SM L1tex wavefront-queue cap that pins
// LDG-based kernels at ~4.5 TB/s), warps compute dot products from smem.
// Block handles 8 rows; K dimension tiled 512 cols x 8 tiles, 4 stages.
template <bool TANH, bool HAS_B1>
__global__ void __launch_bounds__(THREADS)
gemv_kernel(const float* __restrict__ W,
            const float* __restrict__ b0,
            const float* __restrict__ b1,
            const float* __restrict__ h_in,
            float* __restrict__ h_out) {
    extern __shared__ char smem[];
    const uint32_t sbase = smem_u32(smem);

    const int warp = threadIdx.x >> 5;
    const int lane = threadIdx.x & 31;
    const int row0 = blockIdx.x * ROWS;

    // Stage the x vector (16 KB) into shared memory.
    {
        const float4* xg = reinterpret_cast<const float4*>(h_in);
        float4* xs = reinterpret_cast<float4*>(smem + SMEM_X);
        #pragma unroll
        for (int i = threadIdx.x; i < H / 4; i += THREADS)
            xs[i] = xg[i];
    }

    // Init mbarriers (one arriver: the expect_tx call).
    if (threadIdx.x == 0) {
        #pragma unroll
        for (int s = 0; s < STAGES; s++)
            mbar_init(sbase + SMEM_MBAR + s * 8, 1);
    }
    __syncthreads();

    // Prologue: issue the first STAGES tiles.
    if (threadIdx.x == 0) {
        #pragma unroll
        for (int t = 0; t < STAGES; t++) {
            const uint32_t mbar = sbase + SMEM_MBAR + t * 8;
            mbar_expect_tx(mbar, TILE_BYTES);
            #pragma unroll
            for (int r = 0; r < ROWS; r++)
                bulk_cp(sbase + SMEM_STAGE(t) + r * ROW_TILE_BYTES,
                        W + (size_t)(row0 + r) * H + t * C,
                        ROW_TILE_BYTES, mbar);
        }
    }

    float acc[4] = {0.f, 0.f, 0.f, 0.f};

    for (int t = 0; t < T_TILES; t++) {
        const int s = t & (STAGES - 1);
        const uint32_t mbar = sbase + SMEM_MBAR + s * 8;
        mbar_wait(mbar, (t / STAGES) & 1);

        // Warp w computes its row's partial dot over this 512-col tile.
        const float4* wr = reinterpret_cast<const float4*>(
            smem + SMEM_STAGE(s) + warp * ROW_TILE_BYTES);
        const float4* xt = reinterpret_cast<const float4*>(smem + SMEM_X) + t * (C / 4);
        #pragma unroll
        for (int j = 0; j < C / 4 / 32; j++) {
            float4 w4 = wr[lane + j * 32];
            float4 x4 = xt[lane + j * 32];
            acc[j] += w4.x * x4.x + w4.y * x4.y + w4.z * x4.z + w4.w * x4.w;
        }

        __syncthreads();  // all warps done reading stage s

        // Re-arm stage s with tile t+STAGES.
        const int tn = t + STAGES;
        if (threadIdx.x == 0 && tn < T_TILES) {
            mbar_expect_tx(mbar, TILE_BYTES);
            #pragma unroll
            for (int r = 0; r < ROWS; r++)
                bulk_cp(sbase + SMEM_STAGE(s) + r * ROW_TILE_BYTES,
                        W + (size_t)(row0 + r) * H + tn * C,
                        ROW_TILE_BYTES, mbar);
        }
    }

    float acc_all = (acc[0] + acc[1]) + (acc[2] + acc[3]);
    #pragma unroll
    for (int off = 16; off; off >>= 1)
        acc_all += __shfl_down_sync(0xffffffffu, acc_all, off);

    if (lane == 0) {
        const int row = row0 + warp;
        float v = acc_all + b0[row];
        if (HAS_B1) v += b1[row];
        h_out[row] = TANH ? tanhf(v) : v;
    }
}

extern "C" void kernel_launch(void* const* d_in, const int* in_sizes, int n_in,
                              void* d_out, int out_size) {
    const float* x    = (const float*)d_in[0];  // [1, H]
    const float* Wxh  = (const float*)d_in[1];  // [L, H, H]
    const float* bxh  = (const float*)d_in[2];  // [L, H]
    // d_in[3] = Whh — multiplied by a zero vector in the reference; never read.
    const float* bhh  = (const float*)d_in[4];  // [L, H]
    const float* fc_w = (const float*)d_in[5];  // [H, H]
    const float* fc_b = (const float*)d_in[6];  // [H]
    float* out = (float*)d_out;

    cudaFuncSetAttribute(gemv_kernel<true, true>,
                         cudaFuncAttributeMaxDynamicSharedMemorySize, SMEM_TOTAL);
    cudaFuncSetAttribute(gemv_kernel<false, false>,
                         cudaFuncAttributeMaxDynamicSharedMemorySize, SMEM_TOTAL);

    float* hbuf = nullptr;
    cudaGetSymbolAddress((void**)&hbuf, g_h);
    float* h0 = hbuf;      // g_h[0]
    float* h1 = hbuf + H;  // g_h[1]

    const dim3 grid(H / ROWS);   // 512 blocks
    const dim3 block(THREADS);   // 256 threads

    const float* cur = x;
    float* nxt = h0;
    for (int i = 0; i < NUM_LAYERS; i++) {
        gemv_kernel<true, true><<<grid, block, SMEM_TOTAL>>>(
            Wxh + (size_t)i * H * H, bxh + (size_t)i * H, bhh + (size_t)i * H,
            cur, nxt);
        cur = nxt;
        nxt = (nxt == h0) ? h1 : h0;
    }
    // Final linear layer: no tanh, single bias.
    gemv_kernel<false, false><<<grid, block, SMEM_TOTAL>>>(fc_w, fc_b, nullptr, cur, out);
}